// round 12
// baseline (speedup 1.0000x reference)
#include <cuda_runtime.h>
#include <cuda_fp16.h>
#include <cuda_bf16.h>

#define N_NODES 50000
#define NUM_GRAPHS 64
#define ET_MAX (1600000 + N_NODES)
#define NB 196   // scan blocks of 256 (196*256 >= 50000; all co-resident)

// ---------------- scratch (device globals) ----------------
__device__ __half g_XP1[N_NODES * 128];
__device__ float  g_ALs1[N_NODES * 2];
__device__ float  g_ALd1[N_NODES * 2];
__device__ float  g_H1[N_NODES * 128];

__device__ __half g_XP2[N_NODES * 64];
__device__ float  g_ALs2[N_NODES];
__device__ float  g_ALd2[N_NODES];
__device__ float  g_H2[N_NODES * 64];

__device__ int g_deg[N_NODES];
__device__ int g_rowptr[N_NODES + 1];
__device__ int g_cursor[N_NODES];
__device__ int g_srcs[ET_MAX];
__device__ int g_scanincl[NB];
__device__ int g_scanflag[NB];

__device__ unsigned g_mxS1[2], g_mxD1[2], g_mxS2[1], g_mxD2[1];

// ---------------- helpers ----------------
__device__ __forceinline__ unsigned f2ord(float f) {
    unsigned u = __float_as_uint(f);
    return (u & 0x80000000u) ? ~u : (u | 0x80000000u);
}
__device__ __forceinline__ float ord2f(unsigned u) {
    return (u & 0x80000000u) ? __uint_as_float(u & 0x7fffffffu)
                             : __uint_as_float(~u);
}
__device__ __forceinline__ unsigned long long packf2(float x, float y) {
    unsigned long long p;
    asm("mov.b64 %0, {%1, %2};" : "=l"(p) : "f"(x), "f"(y));
    return p;
}
__device__ __forceinline__ void unpackf2(unsigned long long p, float& x, float& y) {
    asm("mov.b64 {%0, %1}, %2;" : "=f"(x), "=f"(y) : "l"(p));
}
__device__ __forceinline__ void ffma2(unsigned long long& d,
                                      unsigned long long a, unsigned long long b) {
    asm("fma.rn.f32x2 %0, %1, %2, %3;" : "=l"(d) : "l"(a), "l"(b), "l"(d));
}

// ---------------- init (split across streams) ----------------
__global__ void k_init_deg() {
    int i = blockIdx.x * blockDim.x + threadIdx.x;
    if (i < N_NODES) g_deg[i] = 1;       // self-loop pre-counted
    if (i < NB) g_scanflag[i] = 0;
}
__global__ void k_init_mx() {
    int i = threadIdx.x;
    if (i < 2) { g_mxS1[i] = 0u; g_mxD1[i] = 0u; }
    if (i < 1) { g_mxS2[i] = 0u; g_mxD2[i] = 0u; }
}

// ---------------- CSR build ----------------
// 4 edges per thread; int4 dst load; 4 independent REDs.
// Self-loops are pre-counted in k_init_deg, so only E real edges here.
__global__ void k_hist4(const int* __restrict__ ei, int E) {
    int base = (blockIdx.x * blockDim.x + threadIdx.x) * 4;
    if (base >= E) return;               // E is a multiple of 4
    int4 d4 = *(const int4*)(ei + E + base);
    atomicAdd(&g_deg[d4.x], 1);
    atomicAdd(&g_deg[d4.y], 1);
    atomicAdd(&g_deg[d4.z], 1);
    atomicAdd(&g_deg[d4.w], 1);
}

// single-launch exclusive scan: per-block scan + all-predecessor lookback.
__global__ void k_scanchain() {
    __shared__ int sd[256];
    __shared__ int rs[256];
    __shared__ int s_prev;
    int b = blockIdx.x, t = threadIdx.x, i = b * 256 + t;
    int v = (i < N_NODES) ? g_deg[i] : 0;
    sd[t] = v;
    __syncthreads();
    for (int o = 1; o < 256; o <<= 1) {
        int x = (t >= o) ? sd[t - o] : 0;
        __syncthreads();
        sd[t] += x;
        __syncthreads();
    }
    int total = sd[255];
    if (t == 0) {
        g_scanincl[b] = total;
        __threadfence();
        atomicExch(&g_scanflag[b], 1);
    }
    int contrib = 0;
    if (t < b) {
        while (atomicAdd(&g_scanflag[t], 0) == 0) {}
        contrib = g_scanincl[t];
    }
    rs[t] = contrib;
    __syncthreads();
    for (int o = 128; o >= 1; o >>= 1) {
        if (t < o) rs[t] += rs[t + o];
        __syncthreads();
    }
    if (t == 0) s_prev = rs[0];
    __syncthreads();
    int off = s_prev + sd[t] - v;
    if (i < N_NODES) { g_rowptr[i] = off; g_cursor[i] = off; }
    if (b == NB - 1 && t == 0) g_rowptr[N_NODES] = s_prev + total;
}

// 4 edges per thread; int4 src/dst loads; 4 INDEPENDENT position atomics
// issued before the dependent stores (MLP 4 vs 1).
__global__ void k_scatter4(const int* __restrict__ ei, int E, int ET) {
    int base = (blockIdx.x * blockDim.x + threadIdx.x) * 4;
    if (base >= ET) return;
    if (base < E) {                      // all 4 are real edges (E mult of 4)
        int4 s4 = *(const int4*)(ei + base);
        int4 d4 = *(const int4*)(ei + E + base);
        int p0 = atomicAdd(&g_cursor[d4.x], 1);
        int p1 = atomicAdd(&g_cursor[d4.y], 1);
        int p2 = atomicAdd(&g_cursor[d4.z], 1);
        int p3 = atomicAdd(&g_cursor[d4.w], 1);
        g_srcs[p0] = s4.x;
        g_srcs[p1] = s4.y;
        g_srcs[p2] = s4.z;
        g_srcs[p3] = s4.w;
    } else {                             // self-loop tail
#pragma unroll
        for (int k = 0; k < 4; k++) {
            int e = base + k;
            if (e < ET) {
                int d = e - E;
                int pos = atomicAdd(&g_cursor[d], 1);
                g_srcs[pos] = d;
            }
        }
    }
}

// ---------------- layer-1 GEMM (f32x2) + logits + fused global max --------
__global__ void k_gemm1(const float* __restrict__ prot,
                        const float* __restrict__ spat,
                        const float* __restrict__ lri,
                        const float* __restrict__ W1,
                        const float* __restrict__ as1,
                        const float* __restrict__ ad1) {
    __shared__ float xs[16][132];
    __shared__ float xst[130][16];
    __shared__ float sps[4][16], spd[4][16];
    const int tid  = threadIdx.x;               // 128
    const int base = blockIdx.x * 16;

    for (int idx = tid; idx < 16 * 130; idx += 128) {
        int n = idx / 130, k = idx % 130;
        int node = base + n;
        float v;
        if (k < 64)      v = prot[node * 64 + k];
        else if (k < 66) v = spat[node * 2 + (k - 64)];
        else             v = lri[node * 64 + (k - 66)];
        xs[n][k] = v;
    }
    __syncthreads();
    for (int idx = tid; idx < 16 * 130; idx += 128) {
        int k = idx / 16, n = idx % 16;
        xst[k][n] = xs[n][k];
    }
    __syncthreads();

    unsigned long long accp[8];
#pragma unroll
    for (int j = 0; j < 8; j++) accp[j] = 0ull;

    for (int k = 0; k < 130; k++) {
        float w = W1[k * 128 + tid];
        unsigned long long wp = packf2(w, w);
        const float2* xr = reinterpret_cast<const float2*>(&xst[k][0]);
#pragma unroll
        for (int j = 0; j < 8; j++) {
            float2 xv = xr[j];
            ffma2(accp[j], packf2(xv.x, xv.y), wp);
        }
    }

    float accv[16];
#pragma unroll
    for (int j = 0; j < 8; j++) unpackf2(accp[j], accv[2 * j], accv[2 * j + 1]);

#pragma unroll
    for (int n = 0; n < 16; n++)
        g_XP1[(base + n) * 128 + tid] = __float2half(accv[n]);

    float as_ = as1[tid], ad_ = ad1[tid];
    int w = tid >> 5, lane = tid & 31;
#pragma unroll
    for (int n = 0; n < 16; n++) {
        float ps = accv[n] * as_;
        float pd = accv[n] * ad_;
#pragma unroll
        for (int o = 16; o >= 1; o >>= 1) {
            ps += __shfl_xor_sync(0xffffffffu, ps, o);
            pd += __shfl_xor_sync(0xffffffffu, pd, o);
        }
        if (lane == 0) { sps[w][n] = ps; spd[w][n] = pd; }
    }
    __syncthreads();
    if (tid < 32) {
        int n = tid & 15, h = tid >> 4;
        int node = base + n;
        float vs = sps[2 * h][n] + sps[2 * h + 1][n];
        float vd = spd[2 * h][n] + spd[2 * h + 1][n];
        g_ALs1[node * 2 + h] = vs;
        g_ALd1[node * 2 + h] = vd;
        float ms = vs, md = vd;
#pragma unroll
        for (int o = 8; o >= 1; o >>= 1) {
            ms = fmaxf(ms, __shfl_xor_sync(0xffffffffu, ms, o, 16));
            md = fmaxf(md, __shfl_xor_sync(0xffffffffu, md, o, 16));
        }
        if (n == 0) {
            atomicMax(&g_mxS1[h], f2ord(ms));
            atomicMax(&g_mxD1[h], f2ord(md));
        }
    }
}

// ---------------- layer-2 GEMM (f32x2) + logits + fused global max --------
__global__ void k_gemm2(const float* __restrict__ W2,
                        const float* __restrict__ as2,
                        const float* __restrict__ ad2) {
    __shared__ float xs[16][128];
    __shared__ float xst[128][16];
    __shared__ float sps[2][16], spd[2][16];
    const int tid  = threadIdx.x;               // 64
    const int base = blockIdx.x * 16;

    for (int idx = tid; idx < 16 * 128; idx += 64) {
        int n = idx / 128, k = idx % 128;
        xs[n][k] = g_H1[(base + n) * 128 + k];
    }
    __syncthreads();
    for (int idx = tid; idx < 16 * 128; idx += 64) {
        int k = idx / 16, n = idx % 16;
        xst[k][n] = xs[n][k];
    }
    __syncthreads();

    unsigned long long accp[8];
#pragma unroll
    for (int j = 0; j < 8; j++) accp[j] = 0ull;

    for (int k = 0; k < 128; k++) {
        float w = W2[k * 64 + tid];
        unsigned long long wp = packf2(w, w);
        const float2* xr = reinterpret_cast<const float2*>(&xst[k][0]);
#pragma unroll
        for (int j = 0; j < 8; j++) {
            float2 xv = xr[j];
            ffma2(accp[j], packf2(xv.x, xv.y), wp);
        }
    }

    float accv[16];
#pragma unroll
    for (int j = 0; j < 8; j++) unpackf2(accp[j], accv[2 * j], accv[2 * j + 1]);

#pragma unroll
    for (int n = 0; n < 16; n++)
        g_XP2[(base + n) * 64 + tid] = __float2half(accv[n]);

    float as_ = as2[tid], ad_ = ad2[tid];
    int w = tid >> 5, lane = tid & 31;
#pragma unroll
    for (int n = 0; n < 16; n++) {
        float ps = accv[n] * as_;
        float pd = accv[n] * ad_;
#pragma unroll
        for (int o = 16; o >= 1; o >>= 1) {
            ps += __shfl_xor_sync(0xffffffffu, ps, o);
            pd += __shfl_xor_sync(0xffffffffu, pd, o);
        }
        if (lane == 0) { sps[w][n] = ps; spd[w][n] = pd; }
    }
    __syncthreads();
    if (tid < 16) {
        int n = tid;
        int node = base + n;
        float vs = sps[0][n] + sps[1][n];
        float vd = spd[0][n] + spd[1][n];
        g_ALs2[node] = vs;
        g_ALd2[node] = vd;
        float ms = vs, md = vd;
#pragma unroll
        for (int o = 8; o >= 1; o >>= 1) {
            ms = fmaxf(ms, __shfl_xor_sync(0x0000ffffu, ms, o, 16));
            md = fmaxf(md, __shfl_xor_sync(0x0000ffffu, md, o, 16));
        }
        if (n == 0) {
            atomicMax(&g_mxS2[0], f2ord(ms));
            atomicMax(&g_mxD2[0], f2ord(md));
        }
    }
}

// ---------------- aggregation layer 1 (H=2): 2 dst/warp, uint4 payload -----
__global__ void k_aggf2(const float* __restrict__ bias) {
    const __half* XP = g_XP1;
    int warp = (blockIdx.x * blockDim.x + threadIdx.x) >> 5;
    int lane = threadIdx.x & 31;
    int d = warp * 2 + (lane >> 4);
    if (d >= N_NODES) return;
    const int sub = lane & 15;
    const int c0  = sub * 8;
    const int h   = c0 >> 6;

    float bx = ord2f(g_mxS1[h]) + ord2f(g_mxD1[h]);
    const float b = (bx > 0.f) ? bx : 0.2f * bx;
    const float ald = g_ALd1[d * 2 + h];
    const int r0 = g_rowptr[d], r1 = g_rowptr[d + 1];

    float acc[2][8] = {};
    float den[2] = {0.f, 0.f};

    int i = r0;
    for (; i + 3 < r1; i += 4) {
        int s[4];
#pragma unroll
        for (int k = 0; k < 4; k++) s[k] = g_srcs[i + k];
        float a[4];
#pragma unroll
        for (int k = 0; k < 4; k++) a[k] = g_ALs1[s[k] * 2 + h];
        uint4 u[4];
#pragma unroll
        for (int k = 0; k < 4; k++) u[k] = *(const uint4*)(XP + s[k] * 128 + c0);
#pragma unroll
        for (int k = 0; k < 4; k++) {
            float x = a[k] + ald;
            float e = (x > 0.f) ? x : 0.2f * x;
            float w = __expf(e - b);
            float2 f0 = __half22float2(*reinterpret_cast<__half2*>(&u[k].x));
            float2 f1 = __half22float2(*reinterpret_cast<__half2*>(&u[k].y));
            float2 f2 = __half22float2(*reinterpret_cast<__half2*>(&u[k].z));
            float2 f3 = __half22float2(*reinterpret_cast<__half2*>(&u[k].w));
            int c = k & 1;
            acc[c][0] = fmaf(w, f0.x, acc[c][0]); acc[c][1] = fmaf(w, f0.y, acc[c][1]);
            acc[c][2] = fmaf(w, f1.x, acc[c][2]); acc[c][3] = fmaf(w, f1.y, acc[c][3]);
            acc[c][4] = fmaf(w, f2.x, acc[c][4]); acc[c][5] = fmaf(w, f2.y, acc[c][5]);
            acc[c][6] = fmaf(w, f3.x, acc[c][6]); acc[c][7] = fmaf(w, f3.y, acc[c][7]);
            den[c] += w;
        }
    }
    for (; i < r1; i++) {
        int s = g_srcs[i];
        float x = g_ALs1[s * 2 + h] + ald;
        float e = (x > 0.f) ? x : 0.2f * x;
        float w = __expf(e - b);
        uint4 u = *(const uint4*)(XP + s * 128 + c0);
        float2 f0 = __half22float2(*reinterpret_cast<__half2*>(&u.x));
        float2 f1 = __half22float2(*reinterpret_cast<__half2*>(&u.y));
        float2 f2 = __half22float2(*reinterpret_cast<__half2*>(&u.z));
        float2 f3 = __half22float2(*reinterpret_cast<__half2*>(&u.w));
        acc[0][0] = fmaf(w, f0.x, acc[0][0]); acc[0][1] = fmaf(w, f0.y, acc[0][1]);
        acc[0][2] = fmaf(w, f1.x, acc[0][2]); acc[0][3] = fmaf(w, f1.y, acc[0][3]);
        acc[0][4] = fmaf(w, f2.x, acc[0][4]); acc[0][5] = fmaf(w, f2.y, acc[0][5]);
        acc[0][6] = fmaf(w, f3.x, acc[0][6]); acc[0][7] = fmaf(w, f3.y, acc[0][7]);
        den[0] += w;
    }

    float dt  = den[0] + den[1];
    float inv = 1.f / dt;
#pragma unroll
    for (int j = 0; j < 8; j++) {
        float a = acc[0][j] + acc[1][j];
        g_H1[d * 128 + c0 + j] = a * inv + bias[c0 + j];
    }
}

// ---------------- aggregation layer 2 (H=1): 2 dst per warp ----------------
__global__ void k_aggf1(const float* __restrict__ bias) {
    const __half* XP = g_XP2;
    int warp = (blockIdx.x * blockDim.x + threadIdx.x) >> 5;
    int lane = threadIdx.x & 31;
    int d = warp * 2 + (lane >> 4);
    if (d >= N_NODES) return;
    const int sub = lane & 15;
    const int c0  = sub * 4;

    float bx = ord2f(g_mxS2[0]) + ord2f(g_mxD2[0]);
    const float b = (bx > 0.f) ? bx : 0.2f * bx;
    const float ald = g_ALd2[d];
    const int r0 = g_rowptr[d], r1 = g_rowptr[d + 1];

    float acc[4][4] = {};
    float den[4] = {0.f, 0.f, 0.f, 0.f};

    int i = r0;
    for (; i + 3 < r1; i += 4) {
        int s[4];
#pragma unroll
        for (int k = 0; k < 4; k++) s[k] = g_srcs[i + k];
        float a[4];
#pragma unroll
        for (int k = 0; k < 4; k++) a[k] = g_ALs2[s[k]];
        uint2 u[4];
#pragma unroll
        for (int k = 0; k < 4; k++) u[k] = *(const uint2*)(XP + s[k] * 64 + c0);
#pragma unroll
        for (int k = 0; k < 4; k++) {
            float x = a[k] + ald;
            float e = (x > 0.f) ? x : 0.2f * x;
            float w = __expf(e - b);
            float2 fa = __half22float2(*reinterpret_cast<__half2*>(&u[k].x));
            float2 fb = __half22float2(*reinterpret_cast<__half2*>(&u[k].y));
            acc[k][0] = fmaf(w, fa.x, acc[k][0]);
            acc[k][1] = fmaf(w, fa.y, acc[k][1]);
            acc[k][2] = fmaf(w, fb.x, acc[k][2]);
            acc[k][3] = fmaf(w, fb.y, acc[k][3]);
            den[k] += w;
        }
    }
    for (; i < r1; i++) {
        int s = g_srcs[i];
        float x = g_ALs2[s] + ald;
        float e = (x > 0.f) ? x : 0.2f * x;
        float w = __expf(e - b);
        uint2 u = *(const uint2*)(XP + s * 64 + c0);
        float2 fa = __half22float2(*reinterpret_cast<__half2*>(&u.x));
        float2 fb = __half22float2(*reinterpret_cast<__half2*>(&u.y));
        acc[0][0] = fmaf(w, fa.x, acc[0][0]);
        acc[0][1] = fmaf(w, fa.y, acc[0][1]);
        acc[0][2] = fmaf(w, fb.x, acc[0][2]);
        acc[0][3] = fmaf(w, fb.y, acc[0][3]);
        den[0] += w;
    }

    float dt  = (den[0] + den[1]) + (den[2] + den[3]);
    float inv = 1.f / dt;
#pragma unroll
    for (int j = 0; j < 4; j++) {
        float a = (acc[0][j] + acc[1][j]) + (acc[2][j] + acc[3][j]);
        g_H2[d * 64 + c0 + j] = a * inv + bias[c0 + j];
    }
}

// ---------------- fused pool + decoder MLP (one block per graph) -----------
__global__ void k_pooldec(const int* __restrict__ batch,
                          const float* __restrict__ Wd1, const float* __restrict__ bd1,
                          const float* __restrict__ Wd2, const float* __restrict__ bd2,
                          float* __restrict__ out) {
    int g = blockIdx.x, tid = threadIdx.x;       // 64 threads
    __shared__ int sb[2];
    __shared__ float p[64], dd[64];
    if (tid < 2) {
        int target = g + tid;
        int lo = 0, hi = N_NODES;
        while (lo < hi) {
            int mid = (lo + hi) >> 1;
            if (batch[mid] < target) lo = mid + 1; else hi = mid;
        }
        sb[tid] = lo;
    }
    __syncthreads();
    int s = sb[0], e = sb[1];
    float acc = 0.f;
    for (int n = s; n < e; n++) acc += g_H2[n * 64 + tid];
    float c = (float)(e - s);
    if (c < 1.f) c = 1.f;
    p[tid] = acc / c;
    __syncthreads();
    float a1 = bd1[tid];
    for (int k = 0; k < 64; k++) a1 = fmaf(p[k], Wd1[k * 64 + tid], a1);
    dd[tid] = fmaxf(a1, 0.f);
    __syncthreads();
    if (tid < 32) {
        float a2 = bd2[tid];
        for (int k = 0; k < 64; k++) a2 = fmaf(dd[k], Wd2[k * 32 + tid], a2);
        out[g * 32 + tid] = a2;
    }
}

// ---------------- launch ----------------
extern "C" void kernel_launch(void* const* d_in, const int* in_sizes, int n_in,
                              void* d_out, int out_size) {
    const float* prot  = (const float*)d_in[0];
    const float* spat  = (const float*)d_in[1];
    const float* lri   = (const float*)d_in[2];
    const int*   ei    = (const int*)d_in[3];
    const int*   batch = (const int*)d_in[4];
    const float* W1   = (const float*)d_in[5];
    const float* as1  = (const float*)d_in[6];
    const float* ad1  = (const float*)d_in[7];
    const float* b1   = (const float*)d_in[8];
    const float* W2   = (const float*)d_in[9];
    const float* as2  = (const float*)d_in[10];
    const float* ad2  = (const float*)d_in[11];
    const float* b2   = (const float*)d_in[12];
    const float* Wd1  = (const float*)d_in[13];
    const float* bd1  = (const float*)d_in[14];
    const float* Wd2  = (const float*)d_in[15];
    const float* bd2  = (const float*)d_in[16];
    float* out = (float*)d_out;

    const int E  = in_sizes[3] / 2;
    const int ET = E + N_NODES;

    static cudaStream_t s2 = 0;
    static cudaEvent_t  evRoot = 0, evCSR = 0;
    if (s2 == 0) {
        cudaStreamCreateWithFlags(&s2, cudaStreamNonBlocking);
        cudaEventCreateWithFlags(&evRoot, cudaEventDisableTiming);
        cudaEventCreateWithFlags(&evCSR, cudaEventDisableTiming);
    }

    // ---- fork immediately: CSR build on s2, feature GEMM on main ----
    cudaEventRecord(evRoot, 0);
    cudaStreamWaitEvent(s2, evRoot, 0);

    k_init_deg<<<NB, 256, 0, s2>>>();
    k_hist4<<<(E / 4 + 255) / 256, 256, 0, s2>>>(ei, E);
    k_scanchain<<<NB, 256, 0, s2>>>();
    k_scatter4<<<(ET / 4 + 256) / 256, 256, 0, s2>>>(ei, E, ET);
    cudaEventRecord(evCSR, s2);

    k_init_mx<<<1, 32>>>();
    k_gemm1<<<(N_NODES + 15) / 16, 128>>>(prot, spat, lri, W1, as1, ad1);

    // ---- join, then the serial tail ----
    cudaStreamWaitEvent(0, evCSR, 0);
    k_aggf2<<<(25000 * 32 + 255) / 256, 256>>>(b1);
    k_gemm2<<<(N_NODES + 15) / 16, 64>>>(W2, as2, ad2);
    k_aggf1<<<(25000 * 32 + 255) / 256, 256>>>(b2);
    k_pooldec<<<NUM_GRAPHS, 64>>>(batch, Wd1, bd1, Wd2, bd2, out);
}

// round 14
// speedup vs baseline: 1.0091x; 1.0091x over previous
#include <cuda_runtime.h>
#include <cuda_fp16.h>
#include <cuda_bf16.h>

#define N_NODES 50000
#define NUM_GRAPHS 64
#define ET_MAX (1600000 + N_NODES)
#define NB 196   // scan blocks of 256 (196*256 >= 50000; all co-resident)

// ---------------- scratch (device globals) ----------------
__device__ __half g_XP1[N_NODES * 128];
__device__ float  g_ALs1[N_NODES * 2];
__device__ float  g_ALd1[N_NODES * 2];
__device__ float  g_H1[N_NODES * 128];

__device__ __half g_XP2[N_NODES * 64];
__device__ float  g_ALs2[N_NODES];
__device__ float  g_ALd2[N_NODES];
__device__ float  g_H2[N_NODES * 64];

__device__ int g_deg[N_NODES];
__device__ int g_rowptr[N_NODES + 1];
__device__ int g_cursor[N_NODES];
__device__ int g_srcs[ET_MAX];
__device__ int g_scanincl[NB];
__device__ int g_scanflag[NB];

__device__ unsigned g_mxS1[2], g_mxD1[2], g_mxS2[1], g_mxD2[1];

// ---------------- helpers ----------------
__device__ __forceinline__ unsigned f2ord(float f) {
    unsigned u = __float_as_uint(f);
    return (u & 0x80000000u) ? ~u : (u | 0x80000000u);
}
__device__ __forceinline__ float ord2f(unsigned u) {
    return (u & 0x80000000u) ? __uint_as_float(u & 0x7fffffffu)
                             : __uint_as_float(~u);
}
__device__ __forceinline__ unsigned long long packf2(float x, float y) {
    unsigned long long p;
    asm("mov.b64 %0, {%1, %2};" : "=l"(p) : "f"(x), "f"(y));
    return p;
}
__device__ __forceinline__ void unpackf2(unsigned long long p, float& x, float& y) {
    asm("mov.b64 {%0, %1}, %2;" : "=f"(x), "=f"(y) : "l"(p));
}
__device__ __forceinline__ void ffma2(unsigned long long& d,
                                      unsigned long long a, unsigned long long b) {
    asm("fma.rn.f32x2 %0, %1, %2, %3;" : "=l"(d) : "l"(a), "l"(b), "l"(d));
}

// ---------------- init (split across streams) ----------------
__global__ void k_init_deg() {
    int i = blockIdx.x * blockDim.x + threadIdx.x;
    if (i < N_NODES) g_deg[i] = 1;       // self-loop pre-counted
    if (i < NB) g_scanflag[i] = 0;
}
__global__ void k_init_mx() {
    int i = threadIdx.x;
    if (i < 2) { g_mxS1[i] = 0u; g_mxD1[i] = 0u; }
    if (i < 1) { g_mxS2[i] = 0u; g_mxD2[i] = 0u; }
}

// ---------------- CSR build ----------------
// Only the E real edges; self-loops handled by init(deg=1) + scanchain emission.
__global__ void k_hist(const int* __restrict__ ei, int E) {
    int e = blockIdx.x * blockDim.x + threadIdx.x;
    if (e >= E) return;
    atomicAdd(&g_deg[ei[E + e]], 1);
}

// single-launch exclusive scan + self-loop emission.
__global__ void k_scanchain() {
    __shared__ int sd[256];
    __shared__ int rs[256];
    __shared__ int s_prev;
    int b = blockIdx.x, t = threadIdx.x, i = b * 256 + t;
    int v = (i < N_NODES) ? g_deg[i] : 0;
    sd[t] = v;
    __syncthreads();
    for (int o = 1; o < 256; o <<= 1) {
        int x = (t >= o) ? sd[t - o] : 0;
        __syncthreads();
        sd[t] += x;
        __syncthreads();
    }
    int total = sd[255];
    if (t == 0) {
        g_scanincl[b] = total;
        __threadfence();
        atomicExch(&g_scanflag[b], 1);
    }
    int contrib = 0;
    if (t < b) {
        while (atomicAdd(&g_scanflag[t], 0) == 0) {}
        contrib = g_scanincl[t];
    }
    rs[t] = contrib;
    __syncthreads();
    for (int o = 128; o >= 1; o >>= 1) {
        if (t < o) rs[t] += rs[t + o];
        __syncthreads();
    }
    if (t == 0) s_prev = rs[0];
    __syncthreads();
    int off = s_prev + sd[t] - v;
    if (i < N_NODES) {
        g_rowptr[i] = off;
        g_srcs[off] = i;                 // self-loop occupies slot 0
        g_cursor[i] = off + 1;
    }
    if (b == NB - 1 && t == 0) g_rowptr[N_NODES] = s_prev + total;
}

__global__ void k_scatter(const int* __restrict__ ei, int E) {
    int e = blockIdx.x * blockDim.x + threadIdx.x;
    if (e >= E) return;
    int s = ei[e];
    int d = ei[E + e];
    int pos = atomicAdd(&g_cursor[d], 1);
    g_srcs[pos] = s;
}

// ---------------- layer-1 GEMM (f32x2) + logits + fused global max --------
__global__ void k_gemm1(const float* __restrict__ prot,
                        const float* __restrict__ spat,
                        const float* __restrict__ lri,
                        const float* __restrict__ W1,
                        const float* __restrict__ as1,
                        const float* __restrict__ ad1) {
    __shared__ float xs[16][132];
    __shared__ float xst[130][16];
    __shared__ float sps[4][16], spd[4][16];
    const int tid  = threadIdx.x;               // 128
    const int base = blockIdx.x * 16;

    for (int idx = tid; idx < 16 * 130; idx += 128) {
        int n = idx / 130, k = idx % 130;
        int node = base + n;
        float v;
        if (k < 64)      v = prot[node * 64 + k];
        else if (k < 66) v = spat[node * 2 + (k - 64)];
        else             v = lri[node * 64 + (k - 66)];
        xs[n][k] = v;
    }
    __syncthreads();
    for (int idx = tid; idx < 16 * 130; idx += 128) {
        int k = idx / 16, n = idx % 16;
        xst[k][n] = xs[n][k];
    }
    __syncthreads();

    unsigned long long accp[8];
#pragma unroll
    for (int j = 0; j < 8; j++) accp[j] = 0ull;

    for (int k = 0; k < 130; k++) {
        float w = W1[k * 128 + tid];
        unsigned long long wp = packf2(w, w);
        const float2* xr = reinterpret_cast<const float2*>(&xst[k][0]);
#pragma unroll
        for (int j = 0; j < 8; j++) {
            float2 xv = xr[j];
            ffma2(accp[j], packf2(xv.x, xv.y), wp);
        }
    }

    float accv[16];
#pragma unroll
    for (int j = 0; j < 8; j++) unpackf2(accp[j], accv[2 * j], accv[2 * j + 1]);

#pragma unroll
    for (int n = 0; n < 16; n++)
        g_XP1[(base + n) * 128 + tid] = __float2half(accv[n]);

    float as_ = as1[tid], ad_ = ad1[tid];
    int w = tid >> 5, lane = tid & 31;
#pragma unroll
    for (int n = 0; n < 16; n++) {
        float ps = accv[n] * as_;
        float pd = accv[n] * ad_;
#pragma unroll
        for (int o = 16; o >= 1; o >>= 1) {
            ps += __shfl_xor_sync(0xffffffffu, ps, o);
            pd += __shfl_xor_sync(0xffffffffu, pd, o);
        }
        if (lane == 0) { sps[w][n] = ps; spd[w][n] = pd; }
    }
    __syncthreads();
    if (tid < 32) {
        int n = tid & 15, h = tid >> 4;
        int node = base + n;
        float vs = sps[2 * h][n] + sps[2 * h + 1][n];
        float vd = spd[2 * h][n] + spd[2 * h + 1][n];
        g_ALs1[node * 2 + h] = vs;
        g_ALd1[node * 2 + h] = vd;
        float ms = vs, md = vd;
#pragma unroll
        for (int o = 8; o >= 1; o >>= 1) {
            ms = fmaxf(ms, __shfl_xor_sync(0xffffffffu, ms, o, 16));
            md = fmaxf(md, __shfl_xor_sync(0xffffffffu, md, o, 16));
        }
        if (n == 0) {
            atomicMax(&g_mxS1[h], f2ord(ms));
            atomicMax(&g_mxD1[h], f2ord(md));
        }
    }
}

// ---------------- layer-2 GEMM (f32x2) + logits + fused global max --------
__global__ void k_gemm2(const float* __restrict__ W2,
                        const float* __restrict__ as2,
                        const float* __restrict__ ad2) {
    __shared__ float xs[16][128];
    __shared__ float xst[128][16];
    __shared__ float sps[2][16], spd[2][16];
    const int tid  = threadIdx.x;               // 64
    const int base = blockIdx.x * 16;

    for (int idx = tid; idx < 16 * 128; idx += 64) {
        int n = idx / 128, k = idx % 128;
        xs[n][k] = g_H1[(base + n) * 128 + k];
    }
    __syncthreads();
    for (int idx = tid; idx < 16 * 128; idx += 64) {
        int k = idx / 16, n = idx % 16;
        xst[k][n] = xs[n][k];
    }
    __syncthreads();

    unsigned long long accp[8];
#pragma unroll
    for (int j = 0; j < 8; j++) accp[j] = 0ull;

    for (int k = 0; k < 128; k++) {
        float w = W2[k * 64 + tid];
        unsigned long long wp = packf2(w, w);
        const float2* xr = reinterpret_cast<const float2*>(&xst[k][0]);
#pragma unroll
        for (int j = 0; j < 8; j++) {
            float2 xv = xr[j];
            ffma2(accp[j], packf2(xv.x, xv.y), wp);
        }
    }

    float accv[16];
#pragma unroll
    for (int j = 0; j < 8; j++) unpackf2(accp[j], accv[2 * j], accv[2 * j + 1]);

#pragma unroll
    for (int n = 0; n < 16; n++)
        g_XP2[(base + n) * 64 + tid] = __float2half(accv[n]);

    float as_ = as2[tid], ad_ = ad2[tid];
    int w = tid >> 5, lane = tid & 31;
#pragma unroll
    for (int n = 0; n < 16; n++) {
        float ps = accv[n] * as_;
        float pd = accv[n] * ad_;
#pragma unroll
        for (int o = 16; o >= 1; o >>= 1) {
            ps += __shfl_xor_sync(0xffffffffu, ps, o);
            pd += __shfl_xor_sync(0xffffffffu, pd, o);
        }
        if (lane == 0) { sps[w][n] = ps; spd[w][n] = pd; }
    }
    __syncthreads();
    if (tid < 16) {
        int n = tid;
        int node = base + n;
        float vs = sps[0][n] + sps[1][n];
        float vd = spd[0][n] + spd[1][n];
        g_ALs2[node] = vs;
        g_ALd2[node] = vd;
        float ms = vs, md = vd;
#pragma unroll
        for (int o = 8; o >= 1; o >>= 1) {
            ms = fmaxf(ms, __shfl_xor_sync(0x0000ffffu, ms, o, 16));
            md = fmaxf(md, __shfl_xor_sync(0x0000ffffu, md, o, 16));
        }
        if (n == 0) {
            atomicMax(&g_mxS2[0], f2ord(ms));
            atomicMax(&g_mxD2[0], f2ord(md));
        }
    }
}

// ---------------- aggregation layer 1 (H=2): 2 dst/warp, uint4 payload -----
__global__ void k_aggf2(const float* __restrict__ bias) {
    const __half* XP = g_XP1;
    int warp = (blockIdx.x * blockDim.x + threadIdx.x) >> 5;
    int lane = threadIdx.x & 31;
    int d = warp * 2 + (lane >> 4);
    if (d >= N_NODES) return;
    const int sub = lane & 15;
    const int c0  = sub * 8;
    const int h   = c0 >> 6;

    float bx = ord2f(g_mxS1[h]) + ord2f(g_mxD1[h]);
    const float b = (bx > 0.f) ? bx : 0.2f * bx;
    const float ald = g_ALd1[d * 2 + h];
    const int r0 = g_rowptr[d], r1 = g_rowptr[d + 1];

    float acc[2][8] = {};
    float den[2] = {0.f, 0.f};

    int i = r0;
    for (; i + 3 < r1; i += 4) {
        int s[4];
#pragma unroll
        for (int k = 0; k < 4; k++) s[k] = g_srcs[i + k];
        float a[4];
#pragma unroll
        for (int k = 0; k < 4; k++) a[k] = g_ALs1[s[k] * 2 + h];
        uint4 u[4];
#pragma unroll
        for (int k = 0; k < 4; k++) u[k] = *(const uint4*)(XP + s[k] * 128 + c0);
#pragma unroll
        for (int k = 0; k < 4; k++) {
            float x = a[k] + ald;
            float e = (x > 0.f) ? x : 0.2f * x;
            float w = __expf(e - b);
            float2 f0 = __half22float2(*reinterpret_cast<__half2*>(&u[k].x));
            float2 f1 = __half22float2(*reinterpret_cast<__half2*>(&u[k].y));
            float2 f2 = __half22float2(*reinterpret_cast<__half2*>(&u[k].z));
            float2 f3 = __half22float2(*reinterpret_cast<__half2*>(&u[k].w));
            int c = k & 1;
            acc[c][0] = fmaf(w, f0.x, acc[c][0]); acc[c][1] = fmaf(w, f0.y, acc[c][1]);
            acc[c][2] = fmaf(w, f1.x, acc[c][2]); acc[c][3] = fmaf(w, f1.y, acc[c][3]);
            acc[c][4] = fmaf(w, f2.x, acc[c][4]); acc[c][5] = fmaf(w, f2.y, acc[c][5]);
            acc[c][6] = fmaf(w, f3.x, acc[c][6]); acc[c][7] = fmaf(w, f3.y, acc[c][7]);
            den[c] += w;
        }
    }
    for (; i < r1; i++) {
        int s = g_srcs[i];
        float x = g_ALs1[s * 2 + h] + ald;
        float e = (x > 0.f) ? x : 0.2f * x;
        float w = __expf(e - b);
        uint4 u = *(const uint4*)(XP + s * 128 + c0);
        float2 f0 = __half22float2(*reinterpret_cast<__half2*>(&u.x));
        float2 f1 = __half22float2(*reinterpret_cast<__half2*>(&u.y));
        float2 f2 = __half22float2(*reinterpret_cast<__half2*>(&u.z));
        float2 f3 = __half22float2(*reinterpret_cast<__half2*>(&u.w));
        acc[0][0] = fmaf(w, f0.x, acc[0][0]); acc[0][1] = fmaf(w, f0.y, acc[0][1]);
        acc[0][2] = fmaf(w, f1.x, acc[0][2]); acc[0][3] = fmaf(w, f1.y, acc[0][3]);
        acc[0][4] = fmaf(w, f2.x, acc[0][4]); acc[0][5] = fmaf(w, f2.y, acc[0][5]);
        acc[0][6] = fmaf(w, f3.x, acc[0][6]); acc[0][7] = fmaf(w, f3.y, acc[0][7]);
        den[0] += w;
    }

    float dt  = den[0] + den[1];
    float inv = 1.f / dt;
#pragma unroll
    for (int j = 0; j < 8; j++) {
        float a = acc[0][j] + acc[1][j];
        g_H1[d * 128 + c0 + j] = a * inv + bias[c0 + j];
    }
}

// ---------------- aggregation layer 2 (H=1): 2 dst per warp ----------------
__global__ void k_aggf1(const float* __restrict__ bias) {
    const __half* XP = g_XP2;
    int warp = (blockIdx.x * blockDim.x + threadIdx.x) >> 5;
    int lane = threadIdx.x & 31;
    int d = warp * 2 + (lane >> 4);
    if (d >= N_NODES) return;
    const int sub = lane & 15;
    const int c0  = sub * 4;

    float bx = ord2f(g_mxS2[0]) + ord2f(g_mxD2[0]);
    const float b = (bx > 0.f) ? bx : 0.2f * bx;
    const float ald = g_ALd2[d];
    const int r0 = g_rowptr[d], r1 = g_rowptr[d + 1];

    float acc[4][4] = {};
    float den[4] = {0.f, 0.f, 0.f, 0.f};

    int i = r0;
    for (; i + 3 < r1; i += 4) {
        int s[4];
#pragma unroll
        for (int k = 0; k < 4; k++) s[k] = g_srcs[i + k];
        float a[4];
#pragma unroll
        for (int k = 0; k < 4; k++) a[k] = g_ALs2[s[k]];
        uint2 u[4];
#pragma unroll
        for (int k = 0; k < 4; k++) u[k] = *(const uint2*)(XP + s[k] * 64 + c0);
#pragma unroll
        for (int k = 0; k < 4; k++) {
            float x = a[k] + ald;
            float e = (x > 0.f) ? x : 0.2f * x;
            float w = __expf(e - b);
            float2 fa = __half22float2(*reinterpret_cast<__half2*>(&u[k].x));
            float2 fb = __half22float2(*reinterpret_cast<__half2*>(&u[k].y));
            acc[k][0] = fmaf(w, fa.x, acc[k][0]);
            acc[k][1] = fmaf(w, fa.y, acc[k][1]);
            acc[k][2] = fmaf(w, fb.x, acc[k][2]);
            acc[k][3] = fmaf(w, fb.y, acc[k][3]);
            den[k] += w;
        }
    }
    for (; i < r1; i++) {
        int s = g_srcs[i];
        float x = g_ALs2[s] + ald;
        float e = (x > 0.f) ? x : 0.2f * x;
        float w = __expf(e - b);
        uint2 u = *(const uint2*)(XP + s * 64 + c0);
        float2 fa = __half22float2(*reinterpret_cast<__half2*>(&u.x));
        float2 fb = __half22float2(*reinterpret_cast<__half2*>(&u.y));
        acc[0][0] = fmaf(w, fa.x, acc[0][0]);
        acc[0][1] = fmaf(w, fa.y, acc[0][1]);
        acc[0][2] = fmaf(w, fb.x, acc[0][2]);
        acc[0][3] = fmaf(w, fb.y, acc[0][3]);
        den[0] += w;
    }

    float dt  = (den[0] + den[1]) + (den[2] + den[3]);
    float inv = 1.f / dt;
#pragma unroll
    for (int j = 0; j < 4; j++) {
        float a = (acc[0][j] + acc[1][j]) + (acc[2][j] + acc[3][j]);
        g_H2[d * 64 + c0 + j] = a * inv + bias[c0 + j];
    }
}

// ---------------- fused pool + decoder MLP (one block per graph) -----------
__global__ void k_pooldec(const int* __restrict__ batch,
                          const float* __restrict__ Wd1, const float* __restrict__ bd1,
                          const float* __restrict__ Wd2, const float* __restrict__ bd2,
                          float* __restrict__ out) {
    int g = blockIdx.x, tid = threadIdx.x;       // 64 threads
    __shared__ int sb[2];
    __shared__ float p[64], dd[64];
    if (tid < 2) {
        int target = g + tid;
        int lo = 0, hi = N_NODES;
        while (lo < hi) {
            int mid = (lo + hi) >> 1;
            if (batch[mid] < target) lo = mid + 1; else hi = mid;
        }
        sb[tid] = lo;
    }
    __syncthreads();
    int s = sb[0], e = sb[1];
    float acc = 0.f;
    for (int n = s; n < e; n++) acc += g_H2[n * 64 + tid];
    float c = (float)(e - s);
    if (c < 1.f) c = 1.f;
    p[tid] = acc / c;
    __syncthreads();
    float a1 = bd1[tid];
    for (int k = 0; k < 64; k++) a1 = fmaf(p[k], Wd1[k * 64 + tid], a1);
    dd[tid] = fmaxf(a1, 0.f);
    __syncthreads();
    if (tid < 32) {
        float a2 = bd2[tid];
        for (int k = 0; k < 64; k++) a2 = fmaf(dd[k], Wd2[k * 32 + tid], a2);
        out[g * 32 + tid] = a2;
    }
}

// ---------------- launch ----------------
extern "C" void kernel_launch(void* const* d_in, const int* in_sizes, int n_in,
                              void* d_out, int out_size) {
    const float* prot  = (const float*)d_in[0];
    const float* spat  = (const float*)d_in[1];
    const float* lri   = (const float*)d_in[2];
    const int*   ei    = (const int*)d_in[3];
    const int*   batch = (const int*)d_in[4];
    const float* W1   = (const float*)d_in[5];
    const float* as1  = (const float*)d_in[6];
    const float* ad1  = (const float*)d_in[7];
    const float* b1   = (const float*)d_in[8];
    const float* W2   = (const float*)d_in[9];
    const float* as2  = (const float*)d_in[10];
    const float* ad2  = (const float*)d_in[11];
    const float* b2   = (const float*)d_in[12];
    const float* Wd1  = (const float*)d_in[13];
    const float* bd1  = (const float*)d_in[14];
    const float* Wd2  = (const float*)d_in[15];
    const float* bd2  = (const float*)d_in[16];
    float* out = (float*)d_out;

    const int E = in_sizes[3] / 2;

    static cudaStream_t s2 = 0;
    static cudaEvent_t  evRoot = 0, evCSR = 0;
    if (s2 == 0) {
        cudaStreamCreateWithFlags(&s2, cudaStreamNonBlocking);
        cudaEventCreateWithFlags(&evRoot, cudaEventDisableTiming);
        cudaEventCreateWithFlags(&evCSR, cudaEventDisableTiming);
    }

    // ---- fork immediately: CSR build on s2, feature GEMM on main ----
    cudaEventRecord(evRoot, 0);
    cudaStreamWaitEvent(s2, evRoot, 0);

    k_init_deg<<<NB, 256, 0, s2>>>();
    k_hist<<<(E + 255) / 256, 256, 0, s2>>>(ei, E);
    k_scanchain<<<NB, 256, 0, s2>>>();
    k_scatter<<<(E + 255) / 256, 256, 0, s2>>>(ei, E);
    cudaEventRecord(evCSR, s2);

    k_init_mx<<<1, 32>>>();
    k_gemm1<<<(N_NODES + 15) / 16, 128>>>(prot, spat, lri, W1, as1, ad1);

    // ---- join, then the serial tail ----
    cudaStreamWaitEvent(0, evCSR, 0);
    k_aggf2<<<(25000 * 32 + 255) / 256, 256>>>(b1);
    k_gemm2<<<(N_NODES + 15) / 16, 64>>>(W2, as2, ad2);
    k_aggf1<<<(25000 * 32 + 255) / 256, 256>>>(b2);
    k_pooldec<<<NUM_GRAPHS, 64>>>(batch, Wd1, bd1, Wd2, bd2, out);
}

// round 16
// speedup vs baseline: 1.0207x; 1.0115x over previous
#include <cuda_runtime.h>
#include <cuda_fp16.h>
#include <cuda_bf16.h>

#define N_NODES 50000
#define NUM_GRAPHS 64
#define ET_MAX (1600000 + N_NODES)
#define NB 196   // scan blocks of 256 (196*256 >= 50000; all co-resident)

// ---------------- scratch (device globals) ----------------
__device__ __half g_XP1[N_NODES * 128];
__device__ float  g_ALs1[N_NODES * 2];
__device__ float  g_ALd1[N_NODES * 2];
__device__ float  g_H1[N_NODES * 128];

__device__ __half g_XP2[N_NODES * 64];
__device__ float  g_ALs2[N_NODES];
__device__ float  g_ALd2[N_NODES];
__device__ float  g_H2[N_NODES * 64];

__device__ int g_deg[N_NODES];
__device__ int g_rowptr[N_NODES + 1];
__device__ int g_cursor[N_NODES];
__device__ int g_srcs[ET_MAX];
__device__ int g_scanincl[NB];
__device__ int g_scanflag[NB];

__device__ unsigned g_mxS1[2], g_mxD1[2], g_mxS2[1], g_mxD2[1];

// ---------------- helpers ----------------
__device__ __forceinline__ unsigned f2ord(float f) {
    unsigned u = __float_as_uint(f);
    return (u & 0x80000000u) ? ~u : (u | 0x80000000u);
}
__device__ __forceinline__ float ord2f(unsigned u) {
    return (u & 0x80000000u) ? __uint_as_float(u & 0x7fffffffu)
                             : __uint_as_float(~u);
}
__device__ __forceinline__ unsigned long long packf2(float x, float y) {
    unsigned long long p;
    asm("mov.b64 %0, {%1, %2};" : "=l"(p) : "f"(x), "f"(y));
    return p;
}
__device__ __forceinline__ void unpackf2(unsigned long long p, float& x, float& y) {
    asm("mov.b64 {%0, %1}, %2;" : "=f"(x), "=f"(y) : "l"(p));
}
__device__ __forceinline__ void ffma2(unsigned long long& d,
                                      unsigned long long a, unsigned long long b) {
    asm("fma.rn.f32x2 %0, %1, %2, %3;" : "=l"(d) : "l"(a), "l"(b), "l"(d));
}

// ---------------- init (split across streams) ----------------
__global__ void k_init_deg() {
    int i = blockIdx.x * blockDim.x + threadIdx.x;
    if (i < N_NODES) g_deg[i] = 1;       // self-loop pre-counted
    if (i < NB) g_scanflag[i] = 0;
}
__global__ void k_init_mx() {
    int i = threadIdx.x;
    if (i < 2) { g_mxS1[i] = 0u; g_mxD1[i] = 0u; }
    if (i < 1) { g_mxS2[i] = 0u; g_mxD2[i] = 0u; }
}

// ---------------- CSR build ----------------
__global__ void k_hist(const int* __restrict__ ei, int E) {
    int e = blockIdx.x * blockDim.x + threadIdx.x;
    if (e >= E) return;
    atomicAdd(&g_deg[ei[E + e]], 1);
}

// single-launch exclusive scan + self-loop emission (verified in R14).
__global__ void k_scanchain() {
    __shared__ int sd[256];
    __shared__ int rs[256];
    __shared__ int s_prev;
    int b = blockIdx.x, t = threadIdx.x, i = b * 256 + t;
    int v = (i < N_NODES) ? g_deg[i] : 0;
    sd[t] = v;
    __syncthreads();
    for (int o = 1; o < 256; o <<= 1) {
        int x = (t >= o) ? sd[t - o] : 0;
        __syncthreads();
        sd[t] += x;
        __syncthreads();
    }
    int total = sd[255];
    if (t == 0) {
        g_scanincl[b] = total;
        __threadfence();
        atomicExch(&g_scanflag[b], 1);
    }
    int contrib = 0;
    if (t < b) {
        while (atomicAdd(&g_scanflag[t], 0) == 0) {}
        contrib = g_scanincl[t];
    }
    rs[t] = contrib;
    __syncthreads();
    for (int o = 128; o >= 1; o >>= 1) {
        if (t < o) rs[t] += rs[t + o];
        __syncthreads();
    }
    if (t == 0) s_prev = rs[0];
    __syncthreads();
    int off = s_prev + sd[t] - v;
    if (i < N_NODES) {
        g_rowptr[i] = off;
        g_srcs[off] = i;                 // self-loop occupies slot 0
        g_cursor[i] = off + 1;
    }
    if (b == NB - 1 && t == 0) g_rowptr[N_NODES] = s_prev + total;
}

__global__ void k_scatter(const int* __restrict__ ei, int E) {
    int e = blockIdx.x * blockDim.x + threadIdx.x;
    if (e >= E) return;
    int s = ei[e];
    int d = ei[E + e];
    int pos = atomicAdd(&g_cursor[d], 1);
    g_srcs[pos] = s;
}

// ---------------- layer-1 GEMM (f32x2) + logits + fused global max --------
__global__ void k_gemm1(const float* __restrict__ prot,
                        const float* __restrict__ spat,
                        const float* __restrict__ lri,
                        const float* __restrict__ W1,
                        const float* __restrict__ as1,
                        const float* __restrict__ ad1) {
    __shared__ float xs[16][132];
    __shared__ float xst[130][16];
    __shared__ float sps[4][16], spd[4][16];
    const int tid  = threadIdx.x;               // 128
    const int base = blockIdx.x * 16;

    for (int idx = tid; idx < 16 * 130; idx += 128) {
        int n = idx / 130, k = idx % 130;
        int node = base + n;
        float v;
        if (k < 64)      v = prot[node * 64 + k];
        else if (k < 66) v = spat[node * 2 + (k - 64)];
        else             v = lri[node * 64 + (k - 66)];
        xs[n][k] = v;
    }
    __syncthreads();
    for (int idx = tid; idx < 16 * 130; idx += 128) {
        int k = idx / 16, n = idx % 16;
        xst[k][n] = xs[n][k];
    }
    __syncthreads();

    unsigned long long accp[8];
#pragma unroll
    for (int j = 0; j < 8; j++) accp[j] = 0ull;

    for (int k = 0; k < 130; k++) {
        float w = W1[k * 128 + tid];
        unsigned long long wp = packf2(w, w);
        const float2* xr = reinterpret_cast<const float2*>(&xst[k][0]);
#pragma unroll
        for (int j = 0; j < 8; j++) {
            float2 xv = xr[j];
            ffma2(accp[j], packf2(xv.x, xv.y), wp);
        }
    }

    float accv[16];
#pragma unroll
    for (int j = 0; j < 8; j++) unpackf2(accp[j], accv[2 * j], accv[2 * j + 1]);

#pragma unroll
    for (int n = 0; n < 16; n++)
        g_XP1[(base + n) * 128 + tid] = __float2half(accv[n]);

    float as_ = as1[tid], ad_ = ad1[tid];
    int w = tid >> 5, lane = tid & 31;
#pragma unroll
    for (int n = 0; n < 16; n++) {
        float ps = accv[n] * as_;
        float pd = accv[n] * ad_;
#pragma unroll
        for (int o = 16; o >= 1; o >>= 1) {
            ps += __shfl_xor_sync(0xffffffffu, ps, o);
            pd += __shfl_xor_sync(0xffffffffu, pd, o);
        }
        if (lane == 0) { sps[w][n] = ps; spd[w][n] = pd; }
    }
    __syncthreads();
    if (tid < 32) {
        int n = tid & 15, h = tid >> 4;
        int node = base + n;
        float vs = sps[2 * h][n] + sps[2 * h + 1][n];
        float vd = spd[2 * h][n] + spd[2 * h + 1][n];
        g_ALs1[node * 2 + h] = vs;
        g_ALd1[node * 2 + h] = vd;
        float ms = vs, md = vd;
#pragma unroll
        for (int o = 8; o >= 1; o >>= 1) {
            ms = fmaxf(ms, __shfl_xor_sync(0xffffffffu, ms, o, 16));
            md = fmaxf(md, __shfl_xor_sync(0xffffffffu, md, o, 16));
        }
        if (n == 0) {
            atomicMax(&g_mxS1[h], f2ord(ms));
            atomicMax(&g_mxD1[h], f2ord(md));
        }
    }
}

// ---------------- layer-2 GEMM (f32x2) + logits + fused global max --------
__global__ void k_gemm2(const float* __restrict__ W2,
                        const float* __restrict__ as2,
                        const float* __restrict__ ad2) {
    __shared__ float xs[16][128];
    __shared__ float xst[128][16];
    __shared__ float sps[2][16], spd[2][16];
    const int tid  = threadIdx.x;               // 64
    const int base = blockIdx.x * 16;

    for (int idx = tid; idx < 16 * 128; idx += 64) {
        int n = idx / 128, k = idx % 128;
        xs[n][k] = g_H1[(base + n) * 128 + k];
    }
    __syncthreads();
    for (int idx = tid; idx < 16 * 128; idx += 64) {
        int k = idx / 16, n = idx % 16;
        xst[k][n] = xs[n][k];
    }
    __syncthreads();

    unsigned long long accp[8];
#pragma unroll
    for (int j = 0; j < 8; j++) accp[j] = 0ull;

    for (int k = 0; k < 128; k++) {
        float w = W2[k * 64 + tid];
        unsigned long long wp = packf2(w, w);
        const float2* xr = reinterpret_cast<const float2*>(&xst[k][0]);
#pragma unroll
        for (int j = 0; j < 8; j++) {
            float2 xv = xr[j];
            ffma2(accp[j], packf2(xv.x, xv.y), wp);
        }
    }

    float accv[16];
#pragma unroll
    for (int j = 0; j < 8; j++) unpackf2(accp[j], accv[2 * j], accv[2 * j + 1]);

#pragma unroll
    for (int n = 0; n < 16; n++)
        g_XP2[(base + n) * 64 + tid] = __float2half(accv[n]);

    float as_ = as2[tid], ad_ = ad2[tid];
    int w = tid >> 5, lane = tid & 31;
#pragma unroll
    for (int n = 0; n < 16; n++) {
        float ps = accv[n] * as_;
        float pd = accv[n] * ad_;
#pragma unroll
        for (int o = 16; o >= 1; o >>= 1) {
            ps += __shfl_xor_sync(0xffffffffu, ps, o);
            pd += __shfl_xor_sync(0xffffffffu, pd, o);
        }
        if (lane == 0) { sps[w][n] = ps; spd[w][n] = pd; }
    }
    __syncthreads();
    if (tid < 16) {
        int n = tid;
        int node = base + n;
        float vs = sps[0][n] + sps[1][n];
        float vd = spd[0][n] + spd[1][n];
        g_ALs2[node] = vs;
        g_ALd2[node] = vd;
        float ms = vs, md = vd;
#pragma unroll
        for (int o = 8; o >= 1; o >>= 1) {
            ms = fmaxf(ms, __shfl_xor_sync(0x0000ffffu, ms, o, 16));
            md = fmaxf(md, __shfl_xor_sync(0x0000ffffu, md, o, 16));
        }
        if (n == 0) {
            atomicMax(&g_mxS2[0], f2ord(ms));
            atomicMax(&g_mxD2[0], f2ord(md));
        }
    }
}

// ---------------- aggregation layer 1 (H=2): 2 dst/warp, uint4 payload -----
__global__ void k_aggf2(const float* __restrict__ bias) {
    const __half* XP = g_XP1;
    int warp = (blockIdx.x * blockDim.x + threadIdx.x) >> 5;
    int lane = threadIdx.x & 31;
    int d = warp * 2 + (lane >> 4);
    if (d >= N_NODES) return;
    const int sub = lane & 15;
    const int c0  = sub * 8;
    const int h   = c0 >> 6;

    float bx = ord2f(g_mxS1[h]) + ord2f(g_mxD1[h]);
    const float b = (bx > 0.f) ? bx : 0.2f * bx;
    const float ald = g_ALd1[d * 2 + h];
    const int r0 = g_rowptr[d], r1 = g_rowptr[d + 1];

    float acc[2][8] = {};
    float den[2] = {0.f, 0.f};

    int i = r0;
    for (; i + 3 < r1; i += 4) {
        int s[4];
#pragma unroll
        for (int k = 0; k < 4; k++) s[k] = g_srcs[i + k];
        float a[4];
#pragma unroll
        for (int k = 0; k < 4; k++) a[k] = g_ALs1[s[k] * 2 + h];
        uint4 u[4];
#pragma unroll
        for (int k = 0; k < 4; k++) u[k] = *(const uint4*)(XP + s[k] * 128 + c0);
#pragma unroll
        for (int k = 0; k < 4; k++) {
            float x = a[k] + ald;
            float e = (x > 0.f) ? x : 0.2f * x;
            float w = __expf(e - b);
            float2 f0 = __half22float2(*reinterpret_cast<__half2*>(&u[k].x));
            float2 f1 = __half22float2(*reinterpret_cast<__half2*>(&u[k].y));
            float2 f2 = __half22float2(*reinterpret_cast<__half2*>(&u[k].z));
            float2 f3 = __half22float2(*reinterpret_cast<__half2*>(&u[k].w));
            int c = k & 1;
            acc[c][0] = fmaf(w, f0.x, acc[c][0]); acc[c][1] = fmaf(w, f0.y, acc[c][1]);
            acc[c][2] = fmaf(w, f1.x, acc[c][2]); acc[c][3] = fmaf(w, f1.y, acc[c][3]);
            acc[c][4] = fmaf(w, f2.x, acc[c][4]); acc[c][5] = fmaf(w, f2.y, acc[c][5]);
            acc[c][6] = fmaf(w, f3.x, acc[c][6]); acc[c][7] = fmaf(w, f3.y, acc[c][7]);
            den[c] += w;
        }
    }
    for (; i < r1; i++) {
        int s = g_srcs[i];
        float x = g_ALs1[s * 2 + h] + ald;
        float e = (x > 0.f) ? x : 0.2f * x;
        float w = __expf(e - b);
        uint4 u = *(const uint4*)(XP + s * 128 + c0);
        float2 f0 = __half22float2(*reinterpret_cast<__half2*>(&u.x));
        float2 f1 = __half22float2(*reinterpret_cast<__half2*>(&u.y));
        float2 f2 = __half22float2(*reinterpret_cast<__half2*>(&u.z));
        float2 f3 = __half22float2(*reinterpret_cast<__half2*>(&u.w));
        acc[0][0] = fmaf(w, f0.x, acc[0][0]); acc[0][1] = fmaf(w, f0.y, acc[0][1]);
        acc[0][2] = fmaf(w, f1.x, acc[0][2]); acc[0][3] = fmaf(w, f1.y, acc[0][3]);
        acc[0][4] = fmaf(w, f2.x, acc[0][4]); acc[0][5] = fmaf(w, f2.y, acc[0][5]);
        acc[0][6] = fmaf(w, f3.x, acc[0][6]); acc[0][7] = fmaf(w, f3.y, acc[0][7]);
        den[0] += w;
    }

    float dt  = den[0] + den[1];
    float inv = 1.f / dt;
#pragma unroll
    for (int j = 0; j < 8; j++) {
        float a = acc[0][j] + acc[1][j];
        g_H1[d * 128 + c0 + j] = a * inv + bias[c0 + j];
    }
}

// ---------------- aggregation layer 2 (H=1): 2 dst/warp, 8-edge window -----
// All 24 loads of the 8-edge batch issue before dependent math (MLP ~48/warp).
__global__ void k_aggf1(const float* __restrict__ bias) {
    const __half* XP = g_XP2;
    int warp = (blockIdx.x * blockDim.x + threadIdx.x) >> 5;
    int lane = threadIdx.x & 31;
    int d = warp * 2 + (lane >> 4);
    if (d >= N_NODES) return;
    const int sub = lane & 15;
    const int c0  = sub * 4;

    float bx = ord2f(g_mxS2[0]) + ord2f(g_mxD2[0]);
    const float b = (bx > 0.f) ? bx : 0.2f * bx;
    const float ald = g_ALd2[d];
    const int r0 = g_rowptr[d], r1 = g_rowptr[d + 1];

    float acc[4][4] = {};
    float den[4] = {0.f, 0.f, 0.f, 0.f};

    int i = r0;
    for (; i + 7 < r1; i += 8) {
        int s[8];
#pragma unroll
        for (int k = 0; k < 8; k++) s[k] = g_srcs[i + k];
        float a[8];
#pragma unroll
        for (int k = 0; k < 8; k++) a[k] = g_ALs2[s[k]];
        uint2 u[8];
#pragma unroll
        for (int k = 0; k < 8; k++) u[k] = *(const uint2*)(XP + s[k] * 64 + c0);
#pragma unroll
        for (int k = 0; k < 8; k++) {
            float x = a[k] + ald;
            float e = (x > 0.f) ? x : 0.2f * x;
            float w = __expf(e - b);
            float2 fa = __half22float2(*reinterpret_cast<__half2*>(&u[k].x));
            float2 fb = __half22float2(*reinterpret_cast<__half2*>(&u[k].y));
            int c = k & 3;
            acc[c][0] = fmaf(w, fa.x, acc[c][0]);
            acc[c][1] = fmaf(w, fa.y, acc[c][1]);
            acc[c][2] = fmaf(w, fb.x, acc[c][2]);
            acc[c][3] = fmaf(w, fb.y, acc[c][3]);
            den[c] += w;
        }
    }
    for (; i < r1; i++) {
        int s = g_srcs[i];
        float x = g_ALs2[s] + ald;
        float e = (x > 0.f) ? x : 0.2f * x;
        float w = __expf(e - b);
        uint2 u = *(const uint2*)(XP + s * 64 + c0);
        float2 fa = __half22float2(*reinterpret_cast<__half2*>(&u.x));
        float2 fb = __half22float2(*reinterpret_cast<__half2*>(&u.y));
        acc[0][0] = fmaf(w, fa.x, acc[0][0]);
        acc[0][1] = fmaf(w, fa.y, acc[0][1]);
        acc[0][2] = fmaf(w, fb.x, acc[0][2]);
        acc[0][3] = fmaf(w, fb.y, acc[0][3]);
        den[0] += w;
    }

    float dt  = (den[0] + den[1]) + (den[2] + den[3]);
    float inv = 1.f / dt;
#pragma unroll
    for (int j = 0; j < 4; j++) {
        float a = (acc[0][j] + acc[1][j]) + (acc[2][j] + acc[3][j]);
        g_H2[d * 64 + c0 + j] = a * inv + bias[c0 + j];
    }
}

// ---------------- fused pool + decoder MLP (one block per graph) -----------
__global__ void k_pooldec(const int* __restrict__ batch,
                          const float* __restrict__ Wd1, const float* __restrict__ bd1,
                          const float* __restrict__ Wd2, const float* __restrict__ bd2,
                          float* __restrict__ out) {
    int g = blockIdx.x, tid = threadIdx.x;       // 64 threads
    __shared__ int sb[2];
    __shared__ float p[64], dd[64];
    if (tid < 2) {
        int target = g + tid;
        int lo = 0, hi = N_NODES;
        while (lo < hi) {
            int mid = (lo + hi) >> 1;
            if (batch[mid] < target) lo = mid + 1; else hi = mid;
        }
        sb[tid] = lo;
    }
    __syncthreads();
    int s = sb[0], e = sb[1];
    float acc = 0.f;
    for (int n = s; n < e; n++) acc += g_H2[n * 64 + tid];
    float c = (float)(e - s);
    if (c < 1.f) c = 1.f;
    p[tid] = acc / c;
    __syncthreads();
    float a1 = bd1[tid];
    for (int k = 0; k < 64; k++) a1 = fmaf(p[k], Wd1[k * 64 + tid], a1);
    dd[tid] = fmaxf(a1, 0.f);
    __syncthreads();
    if (tid < 32) {
        float a2 = bd2[tid];
        for (int k = 0; k < 64; k++) a2 = fmaf(dd[k], Wd2[k * 32 + tid], a2);
        out[g * 32 + tid] = a2;
    }
}

// ---------------- launch ----------------
extern "C" void kernel_launch(void* const* d_in, const int* in_sizes, int n_in,
                              void* d_out, int out_size) {
    const float* prot  = (const float*)d_in[0];
    const float* spat  = (const float*)d_in[1];
    const float* lri   = (const float*)d_in[2];
    const int*   ei    = (const int*)d_in[3];
    const int*   batch = (const int*)d_in[4];
    const float* W1   = (const float*)d_in[5];
    const float* as1  = (const float*)d_in[6];
    const float* ad1  = (const float*)d_in[7];
    const float* b1   = (const float*)d_in[8];
    const float* W2   = (const float*)d_in[9];
    const float* as2  = (const float*)d_in[10];
    const float* ad2  = (const float*)d_in[11];
    const float* b2   = (const float*)d_in[12];
    const float* Wd1  = (const float*)d_in[13];
    const float* bd1  = (const float*)d_in[14];
    const float* Wd2  = (const float*)d_in[15];
    const float* bd2  = (const float*)d_in[16];
    float* out = (float*)d_out;

    const int E = in_sizes[3] / 2;

    static cudaStream_t s2 = 0;
    static cudaEvent_t  evRoot = 0, evCSR = 0;
    if (s2 == 0) {
        cudaStreamCreateWithFlags(&s2, cudaStreamNonBlocking);
        cudaEventCreateWithFlags(&evRoot, cudaEventDisableTiming);
        cudaEventCreateWithFlags(&evCSR, cudaEventDisableTiming);
    }

    // ---- fork immediately: CSR build on s2, feature GEMM on main ----
    cudaEventRecord(evRoot, 0);
    cudaStreamWaitEvent(s2, evRoot, 0);

    k_init_deg<<<NB, 256, 0, s2>>>();
    k_hist<<<(E + 255) / 256, 256, 0, s2>>>(ei, E);
    k_scanchain<<<NB, 256, 0, s2>>>();
    k_scatter<<<(E + 255) / 256, 256, 0, s2>>>(ei, E);
    cudaEventRecord(evCSR, s2);

    k_init_mx<<<1, 32>>>();
    k_gemm1<<<(N_NODES + 15) / 16, 128>>>(prot, spat, lri, W1, as1, ad1);

    // ---- join, then the serial tail ----
    cudaStreamWaitEvent(0, evCSR, 0);
    k_aggf2<<<(25000 * 32 + 255) / 256, 256>>>(b1);
    k_gemm2<<<(N_NODES + 15) / 16, 64>>>(W2, as2, ad2);
    k_aggf1<<<(25000 * 32 + 255) / 256, 256>>>(b2);
    k_pooldec<<<NUM_GRAPHS, 64>>>(batch, Wd1, bd1, Wd2, bd2, out);
}